// round 2
// baseline (speedup 1.0000x reference)
#include <cuda_runtime.h>
#include <cstdint>

// Problem constants (fixed by the dataset problem)
#define B_      256
#define D_      8192
#define S_      8
#define W_      4
#define NSLOTS_ 2048
#define SLEN_   3   // state_len = W-1

// Scratch (device globals per harness rules)
__device__ int g_inv[NSLOTS_];   // slot -> batch index or -1
__device__ int g_idx64;          // 1 if cache_indices is int64, 0 if int32

// ---------------------------------------------------------------------------
// Kernel 0: detect cache_indices element width.
// If int64 (little-endian), every odd 32-bit word is the sign-extension of
// the even word (0 for non-negative slots, -1 for pad). For int32 data the
// odd words are independent slot values — mismatch is certain in practice.
// ---------------------------------------------------------------------------
__global__ void k_detect(const int* __restrict__ idx32) {
    if (threadIdx.x == 0) {
        int is64 = 1;
        for (int i = 0; i < B_; i++) {
            int lo = idx32[2 * i];
            int hi = idx32[2 * i + 1];
            int expect_hi = (lo < 0) ? -1 : 0;
            if (hi != expect_hi) { is64 = 0; break; }
        }
        g_idx64 = is64;
    }
}

__device__ __forceinline__ long long load_idx(const void* p, int b) {
    if (g_idx64) return ((const long long*)p)[b];
    return (long long)((const int*)p)[b];
}

// ---------------------------------------------------------------------------
// Kernel 1: init inverse map
// ---------------------------------------------------------------------------
__global__ void k_init_inv() {
    int i = blockIdx.x * blockDim.x + threadIdx.x;
    if (i < NSLOTS_) g_inv[i] = -1;
}

// ---------------------------------------------------------------------------
// Kernel 2: scatter batch index into inverse map (valid slots only)
// ---------------------------------------------------------------------------
__global__ void k_scatter(const void* __restrict__ cache_idx,
                          const int* __restrict__ pad_p) {
    int b = blockIdx.x * blockDim.x + threadIdx.x;
    if (b < B_) {
        long long slot = load_idx(cache_idx, b);
        long long pad  = (long long)(*pad_p);  // low 32 bits safe for i32/i64 LE
        if (slot != pad && slot >= 0 && slot < NSLOTS_) {
            g_inv[(int)slot] = b;
        }
    }
}

// ---------------------------------------------------------------------------
// Kernel 3: main conv + residual + state update
// One thread per (b, d) row. Fully coalesced:
//   x/out: 32B per thread (2x float4), weight: 16B float4 (L2-resident),
//   states: 3 contiguous floats per thread.
// ---------------------------------------------------------------------------
__global__ void __launch_bounds__(256)
k_conv(const float* __restrict__ x,
       const float* __restrict__ weight,
       const float* __restrict__ conv_states,
       const void* __restrict__ cache_idx,
       const int* __restrict__ res_p,
       const int* __restrict__ pad_p,
       float* __restrict__ out,
       float* __restrict__ out_states) {
    int t = blockIdx.x * blockDim.x + threadIdx.x;   // 0 .. B*D-1
    int d = t & (D_ - 1);
    int b = t >> 13;                                 // log2(D_) = 13

    long long slot = load_idx(cache_idx, b);
    long long pad  = (long long)(*pad_p);
    bool valid = (slot != pad);
    long long safe = (valid && slot >= 0 && slot < NSLOTS_) ? slot : 0;

    // State read (3 floats, contiguous across d)
    const float* sp = conv_states + safe * ((long long)D_ * SLEN_) + (long long)d * SLEN_;
    float c0 = sp[0], c1 = sp[1], c2 = sp[2];

    // x read: 8 contiguous floats
    const float4* xp = reinterpret_cast<const float4*>(x + (long long)t * S_);
    float4 xa = xp[0];
    float4 xb = xp[1];

    // weight: 4 floats per d
    float4 wv = reinterpret_cast<const float4*>(weight)[d];

    float c[11] = {c0, c1, c2, xa.x, xa.y, xa.z, xa.w, xb.x, xb.y, xb.z, xb.w};

    float res = (*res_p != 0) ? 1.0f : 0.0f;

    float o[8];
    #pragma unroll
    for (int s = 0; s < 8; s++) {
        float acc = res * c[s + 3];
        acc = fmaf(c[s + 3], wv.w, acc);
        acc = fmaf(c[s + 2], wv.z, acc);
        acc = fmaf(c[s + 1], wv.y, acc);
        acc = fmaf(c[s + 0], wv.x, acc);
        o[s] = acc;
    }

    float4* op = reinterpret_cast<float4*>(out + (long long)t * S_);
    op[0] = make_float4(o[0], o[1], o[2], o[3]);
    op[1] = make_float4(o[4], o[5], o[6], o[7]);

    // New state = last 3 x values; only valid slots written here.
    if (valid && slot >= 0 && slot < NSLOTS_) {
        float* np = out_states + slot * ((long long)D_ * SLEN_) + (long long)d * SLEN_;
        np[0] = c[8];
        np[1] = c[9];
        np[2] = c[10];
    }
}

// ---------------------------------------------------------------------------
// Kernel 4: copy untouched slots (slot not in cache_indices) old -> new states.
// Per-block uniform predicate (whole block = one slot) -> no divergence.
// D*SLEN = 24576 floats per slot = 6144 float4 = 24 blocks of 256.
// ---------------------------------------------------------------------------
__global__ void __launch_bounds__(256)
k_copy(const float* __restrict__ conv_states,
       float* __restrict__ out_states) {
    int slot = blockIdx.y;
    if (g_inv[slot] >= 0) return;   // slot gets fresh state from k_conv
    int i = blockIdx.x * blockDim.x + threadIdx.x;  // 0..6143
    const float4* src = reinterpret_cast<const float4*>(conv_states + (size_t)slot * D_ * SLEN_);
    float4*       dst = reinterpret_cast<float4*>(out_states + (size_t)slot * D_ * SLEN_);
    dst[i] = src[i];
}

// ---------------------------------------------------------------------------
// Launch
// Inputs: [0]=x f32, [1]=weight f32, [2]=conv_states f32,
//         [3]=cache_indices (int32 or int64), [4]=residual_connection, [5]=pad_slot_id
// Output: [out (B*D*S) | new_conv_states (NSLOTS*D*SLEN)] as f32
// ---------------------------------------------------------------------------
extern "C" void kernel_launch(void* const* d_in, const int* in_sizes, int n_in,
                              void* d_out, int out_size) {
    const float* x   = (const float*)d_in[0];
    const float* wgt = (const float*)d_in[1];
    const float* st  = (const float*)d_in[2];
    const void*  idx = d_in[3];
    const int*   res = (const int*)d_in[4];
    const int*   pad = (const int*)d_in[5];

    float* out        = (float*)d_out;
    float* out_states = out + (size_t)B_ * D_ * S_;

    k_detect<<<1, 32>>>((const int*)idx);
    k_init_inv<<<(NSLOTS_ + 255) / 256, 256>>>();
    k_scatter<<<(B_ + 255) / 256, 256>>>(idx, pad);

    const int total = B_ * D_;
    k_conv<<<total / 256, 256>>>(x, wgt, st, idx, res, pad, out, out_states);

    dim3 cgrid((D_ * SLEN_ / 4) / 256, NSLOTS_);   // (24, 2048)
    k_copy<<<cgrid, 256>>>(st, out_states);
}

// round 3
// speedup vs baseline: 1.1618x; 1.1618x over previous
#include <cuda_runtime.h>
#include <cstdint>

// Problem constants (fixed by the dataset problem)
#define B_      256
#define D_      8192
#define S_      8
#define W_      4
#define NSLOTS_ 2048
#define SLEN_   3   // state_len = W-1

#define CONV_BLOCKS   (B_ * D_ / 256)            // 8192
#define F4_PER_SLOT   (D_ * SLEN_ / 4)           // 6144
#define COPY_PARTS    6                          // 6 blocks * 256 thr * 4 f4 = 6144
#define COPY_BLOCKS   (NSLOTS_ * COPY_PARTS)     // 12288
#define TOTAL_BLOCKS  (CONV_BLOCKS + COPY_BLOCKS)

// Scratch (device globals per harness rules)
__device__ int g_inv[NSLOTS_];   // slot -> batch index or -1
__device__ int g_idx64;          // 1 if cache_indices is int64, 0 if int32

// ---------------------------------------------------------------------------
// Prep kernel: detect index width + build slot->batch inverse map.
// 8 blocks x 256 threads = 2048 threads (one per slot). Each block
// independently detects the index element width (no cross-block ordering),
// loads all 256 indices to smem, and each thread scans for its slot.
// ---------------------------------------------------------------------------
__global__ void __launch_bounds__(256)
k_prep(const int* __restrict__ idx32, const int* __restrict__ pad_p) {
    __shared__ int s_idx[B_];
    __shared__ int s_is64;
    int tid  = threadIdx.x;
    int slot = blockIdx.x * 256 + tid;

    if (tid == 0) {
        // int64 LE: odd word is sign-extension of even word. For int32 data
        // (independent slot values from a permutation) this fails immediately.
        int is64 = 1;
        for (int i = 0; i < B_; i++) {
            int lo = idx32[2 * i];
            int hi = idx32[2 * i + 1];
            if (hi != ((lo < 0) ? -1 : 0)) { is64 = 0; break; }
        }
        s_is64 = is64;
        if (blockIdx.x == 0) g_idx64 = is64;
    }
    __syncthreads();
    int is64 = s_is64;
    int pad  = *pad_p;   // low 32 bits: correct for int32 and int64 LE

    // Low 32 bits carry the full value (slots are 0..2047 or pad=-1).
    s_idx[tid] = is64 ? idx32[2 * tid] : idx32[tid];
    __syncthreads();

    int inv = -1;
    #pragma unroll 8
    for (int b = 0; b < B_; b++) {
        int v = s_idx[b];
        if (v == slot && v != pad) inv = b;   // last match wins (matches .at[].set)
    }
    g_inv[slot] = inv;
}

// ---------------------------------------------------------------------------
// Fused main kernel.
// blockIdx.x <  CONV_BLOCKS : conv + residual + state write (1 thr / (b,d))
// blockIdx.x >= CONV_BLOCKS : copy untouched slots old->new states
// Output regions are disjoint; copy skips slots that get fresh state.
// ---------------------------------------------------------------------------
__global__ void __launch_bounds__(256)
k_main(const float* __restrict__ x,
       const float* __restrict__ weight,
       const float* __restrict__ conv_states,
       const void* __restrict__ cache_idx,
       const int* __restrict__ res_p,
       const int* __restrict__ pad_p,
       float* __restrict__ out,
       float* __restrict__ out_states) {
    if (blockIdx.x < CONV_BLOCKS) {
        // ---- conv part ----
        int t = blockIdx.x * 256 + threadIdx.x;   // 0 .. B*D-1
        int d = t & (D_ - 1);
        int b = t >> 13;                          // log2(D_) = 13

        long long slot;
        if (g_idx64) slot = ((const long long*)cache_idx)[b];
        else         slot = (long long)((const int*)cache_idx)[b];
        long long pad = (long long)(*pad_p);
        bool valid = (slot != pad) && (slot >= 0) && (slot < NSLOTS_);
        long long safe = valid ? slot : 0;

        const float* sp = conv_states + safe * ((long long)D_ * SLEN_) + (long long)d * SLEN_;
        float c0 = sp[0], c1 = sp[1], c2 = sp[2];

        const float4* xp = reinterpret_cast<const float4*>(x + (long long)t * S_);
        float4 xa = xp[0];
        float4 xb = xp[1];

        float4 wv = reinterpret_cast<const float4*>(weight)[d];

        float c[11] = {c0, c1, c2, xa.x, xa.y, xa.z, xa.w, xb.x, xb.y, xb.z, xb.w};
        float res = (*res_p != 0) ? 1.0f : 0.0f;

        float o[8];
        #pragma unroll
        for (int s = 0; s < 8; s++) {
            float acc = res * c[s + 3];
            acc = fmaf(c[s + 3], wv.w, acc);
            acc = fmaf(c[s + 2], wv.z, acc);
            acc = fmaf(c[s + 1], wv.y, acc);
            acc = fmaf(c[s + 0], wv.x, acc);
            o[s] = acc;
        }

        float4* op = reinterpret_cast<float4*>(out + (long long)t * S_);
        op[0] = make_float4(o[0], o[1], o[2], o[3]);
        op[1] = make_float4(o[4], o[5], o[6], o[7]);

        if (valid) {
            float* np = out_states + slot * ((long long)D_ * SLEN_) + (long long)d * SLEN_;
            np[0] = c[8];
            np[1] = c[9];
            np[2] = c[10];
        }
    } else {
        // ---- copy part: untouched slots old state -> new state ----
        int cb   = blockIdx.x - CONV_BLOCKS;
        int slot = cb / COPY_PARTS;
        int part = cb - slot * COPY_PARTS;
        if (g_inv[slot] >= 0) return;   // slot gets fresh state from conv part

        size_t base = (size_t)slot * F4_PER_SLOT + (size_t)part * 1024 + threadIdx.x;
        const float4* src = reinterpret_cast<const float4*>(conv_states) + base;
        float4*       dst = reinterpret_cast<float4*>(out_states) + base;
        // 4x batched loads for MLP, then stores
        float4 v0 = src[0];
        float4 v1 = src[256];
        float4 v2 = src[512];
        float4 v3 = src[768];
        dst[0]   = v0;
        dst[256] = v1;
        dst[512] = v2;
        dst[768] = v3;
    }
}

// ---------------------------------------------------------------------------
// Launch
// Inputs: [0]=x f32, [1]=weight f32, [2]=conv_states f32,
//         [3]=cache_indices (int32 or int64), [4]=residual_connection, [5]=pad_slot_id
// Output: [out (B*D*S) | new_conv_states (NSLOTS*D*SLEN)] as f32
// ---------------------------------------------------------------------------
extern "C" void kernel_launch(void* const* d_in, const int* in_sizes, int n_in,
                              void* d_out, int out_size) {
    const float* x   = (const float*)d_in[0];
    const float* wgt = (const float*)d_in[1];
    const float* st  = (const float*)d_in[2];
    const void*  idx = d_in[3];
    const int*   res = (const int*)d_in[4];
    const int*   pad = (const int*)d_in[5];

    float* out        = (float*)d_out;
    float* out_states = out + (size_t)B_ * D_ * S_;

    k_prep<<<NSLOTS_ / 256, 256>>>((const int*)idx, pad);
    k_main<<<TOTAL_BLOCKS, 256>>>(x, wgt, st, idx, res, pad, out, out_states);
}

// round 4
// speedup vs baseline: 1.2236x; 1.0532x over previous
#include <cuda_runtime.h>
#include <cstdint>

// Problem constants (fixed by the dataset problem)
#define B_      256
#define D_      8192
#define S_      8
#define W_      4
#define NSLOTS_ 2048
#define SLEN_   3   // state_len = W-1

#define CONV_BLOCKS   (B_ * D_ / 256)            // 8192 (32 blocks per batch row)
#define F4_PER_SLOT   (D_ * SLEN_ / 4)           // 6144
#define COPY_PARTS    6                          // 6 blocks * 256 thr * 4 f4 = 6144
#define COPY_BLOCKS   (NSLOTS_ * COPY_PARTS)     // 12288
#define TOTAL_BLOCKS  (CONV_BLOCKS + COPY_BLOCKS)

// ---------------------------------------------------------------------------
// Single fused kernel. Every block is self-sufficient (no prep kernel):
//  - per-block index-width detection (int32 vs int64) on the first 1 KB,
//    which is in-bounds for either width. Under int32 a false "is64" would
//    need 128 distinct permutation values at odd words to all be 0: impossible.
//  - conv blocks   (blockIdx <  CONV_BLOCKS): 1 thread per (b,d) row.
//  - copy blocks   (blockIdx >= CONV_BLOCKS): membership test (is this slot in
//    cache_indices?) via 256-thread compare + __syncthreads_or, then stream-copy
//    the untouched slot's old state to the new-state region.
// Output regions are disjoint across all blocks.
// ---------------------------------------------------------------------------
__global__ void __launch_bounds__(256)
k_main(const float* __restrict__ x,
       const float* __restrict__ weight,
       const float* __restrict__ conv_states,
       const void* __restrict__ cache_idx,
       const int* __restrict__ res_p,
       const int* __restrict__ pad_p,
       float* __restrict__ out,
       float* __restrict__ out_states) {
    const int tid = threadIdx.x;
    const int* idx32 = (const int*)cache_idx;

    // ---- per-block index width detection (first 1 KB only: always in-bounds)
    int lo = 0, hi = 0;
    if (tid < 128) {
        lo = idx32[2 * tid];
        hi = idx32[2 * tid + 1];
    }
    bool pair_ok = (tid < 128) ? (hi == ((lo < 0) ? -1 : 0)) : true;
    int is64 = __syncthreads_and(pair_ok);

    const int pad32 = *pad_p;   // low 32 bits: correct for int32 and int64 LE

    if (blockIdx.x < CONV_BLOCKS) {
        // ---- conv + residual + fresh-state write ----
        int t = blockIdx.x * 256 + tid;      // 0 .. B*D-1
        int d = t & (D_ - 1);
        int b = blockIdx.x >> 5;             // 32 blocks per batch row

        long long slot;
        if (is64) slot = ((const long long*)cache_idx)[b];
        else      slot = (long long)idx32[b];
        long long pad = (long long)pad32;
        bool valid = (slot != pad) && (slot >= 0) && (slot < NSLOTS_);
        long long safe = valid ? slot : 0;

        const float* sp = conv_states + safe * ((long long)D_ * SLEN_) + (long long)d * SLEN_;
        float c0 = sp[0], c1 = sp[1], c2 = sp[2];

        const float4* xp = reinterpret_cast<const float4*>(x + (long long)t * S_);
        float4 xa = xp[0];
        float4 xb = xp[1];

        float4 wv = reinterpret_cast<const float4*>(weight)[d];

        float c[11] = {c0, c1, c2, xa.x, xa.y, xa.z, xa.w, xb.x, xb.y, xb.z, xb.w};
        float res = (*res_p != 0) ? 1.0f : 0.0f;

        float o[8];
        #pragma unroll
        for (int s = 0; s < 8; s++) {
            float acc = res * c[s + 3];
            acc = fmaf(c[s + 3], wv.w, acc);
            acc = fmaf(c[s + 2], wv.z, acc);
            acc = fmaf(c[s + 1], wv.y, acc);
            acc = fmaf(c[s + 0], wv.x, acc);
            o[s] = acc;
        }

        float4* op = reinterpret_cast<float4*>(out + (long long)t * S_);
        op[0] = make_float4(o[0], o[1], o[2], o[3]);
        op[1] = make_float4(o[4], o[5], o[6], o[7]);

        if (valid) {
            float* np = out_states + slot * ((long long)D_ * SLEN_) + (long long)d * SLEN_;
            np[0] = c[8];
            np[1] = c[9];
            np[2] = c[10];
        }
    } else {
        // ---- copy untouched slots: old state -> new state ----
        int cb   = blockIdx.x - CONV_BLOCKS;
        int slot = cb / COPY_PARTS;
        int part = cb - slot * COPY_PARTS;

        // Membership test: is `slot` a valid target of cache_indices?
        // (values fit in 32 bits for both widths; L2-resident after 1st block)
        int v = is64 ? idx32[2 * tid] : idx32[tid];
        bool hit = (v == slot) && (v != pad32);
        if (__syncthreads_or(hit)) return;   // slot gets fresh state from conv blocks

        size_t base = (size_t)slot * F4_PER_SLOT + (size_t)part * 1024 + tid;
        const float4* src = reinterpret_cast<const float4*>(conv_states) + base;
        float4*       dst = reinterpret_cast<float4*>(out_states) + base;
        float4 v0 = src[0];
        float4 v1 = src[256];
        float4 v2 = src[512];
        float4 v3 = src[768];
        dst[0]   = v0;
        dst[256] = v1;
        dst[512] = v2;
        dst[768] = v3;
    }
}

// ---------------------------------------------------------------------------
// Launch — single kernel, single graph node.
// Inputs: [0]=x f32, [1]=weight f32, [2]=conv_states f32,
//         [3]=cache_indices (int32 or int64), [4]=residual_connection, [5]=pad_slot_id
// Output: [out (B*D*S) | new_conv_states (NSLOTS*D*SLEN)] as f32
// ---------------------------------------------------------------------------
extern "C" void kernel_launch(void* const* d_in, const int* in_sizes, int n_in,
                              void* d_out, int out_size) {
    const float* x   = (const float*)d_in[0];
    const float* wgt = (const float*)d_in[1];
    const float* st  = (const float*)d_in[2];
    const void*  idx = d_in[3];
    const int*   res = (const int*)d_in[4];
    const int*   pad = (const int*)d_in[5];

    float* out        = (float*)d_out;
    float* out_states = out + (size_t)B_ * D_ * S_;

    k_main<<<TOTAL_BLOCKS, 256>>>(x, wgt, st, idx, res, pad, out, out_states);
}